// round 7
// baseline (speedup 1.0000x reference)
#include <cuda_runtime.h>
#include <stdint.h>

// Geometry fixed by the problem: outputs/masks are [2,1,64,256,256]
#define HH 256
#define WW 256
#define BATCH 2
#define SLICES 128                 // 2*64 independent 2D slices
#define WPR 8                      // 32-bit words per 256-px row
#define NWORDS (HH * WPR)          // 2048 words per slice bitmask
#define NPIX (HH * WW)             // 65536 px per slice
#define NCTA3 1024                 // decode/pack grid (8 CTAs per slice)

// ---- gmem scratch (static __device__, allowed) ----
__device__ uint32_t g_mb[SLICES][NWORDS];     // mask bits        (1 MB)
__device__ uint32_t g_eb[SLICES][NWORDS];     // edge bits        (1 MB)
__device__ int      g_base[SLICES][NWORDS];   // per-word LUT base, incl. extra (2 MB)
__device__ uint32_t g_hm[SLICES][NWORDS];     // per-word K==ktop bitmask (1 MB)
__device__ uint32_t g_pl[5][SLICES][NWORDS];  // slow-path planes (written only when needed)
__device__ int      g_extra[SLICES];
__device__ double   g_cta[NCTA3][3];          // per-CTA partials: intersect, in_area, tgt_area
__device__ unsigned g_ticket = 0;

// ================= K1: pack masks to bits (pure streaming) =================
__global__ __launch_bounds__(256, 8)
void pack_kernel(const int* __restrict__ mskp) {
    const int tid = threadIdx.x;
    const int lane = tid & 31;
    const int4* mp4 = reinterpret_cast<const int4*>(mskp) + (size_t)blockIdx.x * 2048;
    uint32_t* mbflat = &g_mb[0][0];
    const size_t wbase = (size_t)blockIdx.x * 256;
#pragma unroll
    for (int i = 0; i < 8; i++) {
        int g = i * 256 + tid;
        int4 v = mp4[g];
        unsigned nib = (v.x != 0 ? 1u : 0u) | (v.y != 0 ? 2u : 0u)
                     | (v.z != 0 ? 4u : 0u) | (v.w != 0 ? 8u : 0u);
        unsigned w = nib << ((lane & 7) * 4);
        w |= __shfl_xor_sync(0xffffffffu, w, 1);
        w |= __shfl_xor_sync(0xffffffffu, w, 2);
        w |= __shfl_xor_sync(0xffffffffu, w, 4);
        if ((lane & 7) == 0) mbflat[wbase + (g >> 3)] = w;
    }
}

// ================= K2: per-slice cascade + per-word decode metadata =========
__global__ __launch_bounds__(1024, 1)
void cascade_kernel() {
    __shared__ uint32_t mb[NWORDS];
    __shared__ uint32_t buf[2][NWORDS];

    const int slice = blockIdx.x;
    const int tid = threadIdx.x;

    const uint32_t* gm = g_mb[slice];
#pragma unroll
    for (int j = 0; j < 2; j++) {
        int idx = j * 1024 + tid;
        mb[idx] = gm[idx];
    }
    __syncthreads();

    // thread owns a quarter-row: 2 consecutive words
    const int row = tid >> 2;
    const int cw0 = (tid & 3) * 2;
    const int wb = row * WPR + cw0;

    uint32_t P0[2], P1[2], P2[2], P3[2], P4[2];  // coverage count K, bit-sliced

    // edge = m & ~(up & down & left & right), zero padded
#pragma unroll
    for (int j = 0; j < 2; j++) {
        int cw = cw0 + j, gw = wb + j;
        uint32_t m  = mb[gw];
        uint32_t up = row            ? mb[gw - WPR] : 0u;
        uint32_t dn = (row < HH - 1) ? mb[gw + WPR] : 0u;
        uint32_t pv = cw             ? mb[gw - 1]   : 0u;
        uint32_t nx = (cw < WPR - 1) ? mb[gw + 1]   : 0u;
        uint32_t lf = (m << 1) | (pv >> 31);
        uint32_t rt = (m >> 1) | (nx << 31);
        uint32_t e = m & ~(up & dn & lf & rt);
        buf[0][gw] = e;
        g_eb[slice][gw] = e;
        P0[j] = 0u; P1[j] = 0u; P2[j] = 0u; P3[j] = 0u; P4[j] = 0u;
    }
    __syncthreads();

    // cascaded 3x3 OR-dilations with saturation early-exit
    int extra = 0;
    int sb = 0;
    for (int r = 1; r <= 20; r++) {
        const uint32_t* src = buf[sb];
        uint32_t* dst = buf[sb ^ 1];
        uint32_t va[4];
#pragma unroll
        for (int k = 0; k < 4; k++) {
            int cw = cw0 + k - 1;
            uint32_t v = 0u;
            if (cw >= 0 && cw < WPR) {
                int gw = row * WPR + cw;
                v = src[gw];
                if (row)          v |= src[gw - WPR];
                if (row < HH - 1) v |= src[gw + WPR];
            }
            va[k] = v;
        }
        uint32_t allw = 0xffffffffu;
#pragma unroll
        for (int j = 0; j < 2; j++) {
            uint32_t c = va[j + 1];
            uint32_t nw = c | (c << 1) | (va[j] >> 31) | (c >> 1) | (va[j + 2] << 31);
            dst[wb + j] = nw;
            allw &= nw;
            uint32_t cy = nw, t;             // ripple-carry +1 where covered
            t = P0[j] & cy; P0[j] ^= cy; cy = t;
            t = P1[j] & cy; P1[j] ^= cy; cy = t;
            t = P2[j] & cy; P2[j] ^= cy; cy = t;
            t = P3[j] & cy; P3[j] ^= cy; cy = t;
            P4[j] ^= cy;
        }
        sb ^= 1;
        if (__syncthreads_and(allw == 0xffffffffu)) { extra = 20 - r; break; }
    }
    if (tid == 0) g_extra[slice] = extra;

    // per-word decode metadata: acc = K + edge, K in {kt-1, kt} per word (typical)
#pragma unroll
    for (int j = 0; j < 2; j++) {
        int gw = wb + j;
        uint32_t p0 = P0[j], p1 = P1[j], p2 = P2[j], p3 = P3[j], p4 = P4[j];
        unsigned kt = ((p0 >> 31) & 1u) | (((p1 >> 31) & 1u) << 1)
                    | (((p2 >> 31) & 1u) << 2) | (((p3 >> 31) & 1u) << 3)
                    | (((p4 >> 31) & 1u) << 4);
        uint32_t mhi = ((kt & 1u)  ? p0 : ~p0) & ((kt & 2u)  ? p1 : ~p1)
                     & ((kt & 4u)  ? p2 : ~p2) & ((kt & 8u)  ? p3 : ~p3)
                     & ((kt & 16u) ? p4 : ~p4);
        uint32_t mlo = 0u;
        if (kt) {
            unsigned kl = kt - 1u;
            mlo = ((kl & 1u)  ? p0 : ~p0) & ((kl & 2u)  ? p1 : ~p1)
                & ((kl & 4u)  ? p2 : ~p2) & ((kl & 8u)  ? p3 : ~p3)
                & ((kl & 16u) ? p4 : ~p4);
        }
        bool valid = (mhi | mlo) == 0xffffffffu;
        g_base[slice][gw] = valid ? ((int)kt - 1 + extra) : -100;
        g_hm[slice][gw] = mhi;
        if (!valid) {                        // rare slow-path spill
            g_pl[0][slice][gw] = p0;
            g_pl[1][slice][gw] = p1;
            g_pl[2][slice][gw] = p2;
            g_pl[3][slice][gw] = p3;
            g_pl[4][slice][gw] = p4;
        }
    }
}

// ================= K3: decode + weighted sums (pure streaming) ===============
__global__ __launch_bounds__(256, 4)
void decode_kernel(const float* __restrict__ outp, float* __restrict__ out) {
    __shared__ float lut[64];
    __shared__ double r0s[8], r1s[8], r2s[8];
    __shared__ int s_last;

    const int cta = blockIdx.x;
    const int slice = cta >> 3;
    const int part = cta & 7;
    const int tid = threadIdx.x;
    const int lane = tid & 31;
    const int wid = tid >> 5;

    // weight LUT: acc in 0..21; dist=(22-acc)/22; w=2/(1+exp(10*dist)); padded
    if (tid < 64) {
        int a = tid < 22 ? tid : 21;
        float dist = (22.0f - (float)a) / 22.0f;
        lut[tid] = 2.0f / (1.0f + expf(10.0f * dist));
    }
    __syncthreads();

    const float4* op4 = reinterpret_cast<const float4*>(outp)
                      + (size_t)slice * (NPIX / 4) + part * 2048;
    const int extra = g_extra[slice];
    float s_ia = 0.f, s_in = 0.f, s_ta = 0.f;

#pragma unroll
    for (int k = 0; k < 8; k++) {
        int g = k * 256 + tid;               // float4 group within this part
        float4 v = op4[g];
        int lw = part * 256 + (g >> 3);      // word within slice
        int i0 = (g & 7) * 4;
        int base = g_base[slice][lw];
        uint32_t qm = g_mb[slice][lw] >> i0;
        uint32_t qe = g_eb[slice][lw] >> i0;
        float vv[4] = {v.x, v.y, v.z, v.w};
        if (base != -100) {
            uint32_t qh = g_hm[slice][lw] >> i0;
#pragma unroll
            for (int e = 0; e < 4; e++) {
                int idx = base + (int)((qh >> e) & 1u) + (int)((qe >> e) & 1u);
                float w = lut[idx];
                float f = vv[e] * w;
                s_ia += f;
                if ((qm >> e) & 1u) { s_in += f; s_ta += w; }
            }
        } else {
            uint32_t q0 = g_pl[0][slice][lw] >> i0;
            uint32_t q1 = g_pl[1][slice][lw] >> i0;
            uint32_t q2 = g_pl[2][slice][lw] >> i0;
            uint32_t q3 = g_pl[3][slice][lw] >> i0;
            uint32_t q4 = g_pl[4][slice][lw] >> i0;
#pragma unroll
            for (int e = 0; e < 4; e++) {
                unsigned a = ((q0 >> e) & 1u)
                           | (((q1 >> e) & 1u) << 1)
                           | (((q2 >> e) & 1u) << 2)
                           | (((q3 >> e) & 1u) << 3)
                           | (((q4 >> e) & 1u) << 4);
                a += ((qe >> e) & 1u) + extra;
                float w = lut[a];
                float f = vv[e] * w;
                s_ia += f;
                if ((qm >> e) & 1u) { s_in += f; s_ta += w; }
            }
        }
    }

    // CTA reduce -> g_cta[cta]
    double d0 = (double)s_in, d1 = (double)s_ia, d2 = (double)s_ta;
#pragma unroll
    for (int o = 16; o > 0; o >>= 1) {
        d0 += __shfl_down_sync(0xffffffffu, d0, o);
        d1 += __shfl_down_sync(0xffffffffu, d1, o);
        d2 += __shfl_down_sync(0xffffffffu, d2, o);
    }
    if (lane == 0) { r0s[wid] = d0; r1s[wid] = d1; r2s[wid] = d2; }
    __syncthreads();
    if (wid == 0) {
        double a0 = (lane < 8) ? r0s[lane] : 0.0;
        double a1 = (lane < 8) ? r1s[lane] : 0.0;
        double a2 = (lane < 8) ? r2s[lane] : 0.0;
#pragma unroll
        for (int o = 4; o > 0; o >>= 1) {
            a0 += __shfl_down_sync(0xffffffffu, a0, o);
            a1 += __shfl_down_sync(0xffffffffu, a1, o);
            a2 += __shfl_down_sync(0xffffffffu, a2, o);
        }
        if (lane == 0) {
            g_cta[cta][0] = a0;
            g_cta[cta][1] = a1;
            g_cta[cta][2] = a2;
        }
    }

    // last-arriving CTA finalizes the scalar loss
    if (tid == 0) {
        __threadfence();
        unsigned t = atomicAdd(&g_ticket, 1u);
        s_last = (t == NCTA3 - 1);
    }
    __syncthreads();
    if (s_last) {
        __threadfence();
        __shared__ double fin[3][8];
        double loss = 0.0;
        for (int b = 0; b < BATCH; b++) {
            // batch b owns CTAs [b*512, b*512+512)
            int j0 = b * 512 + tid;
            double i0 = g_cta[j0][0] + g_cta[j0 + 256][0];
            double a0 = g_cta[j0][1] + g_cta[j0 + 256][1];
            double t0 = g_cta[j0][2] + g_cta[j0 + 256][2];
#pragma unroll
            for (int o = 16; o > 0; o >>= 1) {
                i0 += __shfl_down_sync(0xffffffffu, i0, o);
                a0 += __shfl_down_sync(0xffffffffu, a0, o);
                t0 += __shfl_down_sync(0xffffffffu, t0, o);
            }
            if (lane == 0) { fin[0][wid] = i0; fin[1][wid] = a0; fin[2][wid] = t0; }
            __syncthreads();
            if (tid == 0) {
                double I = 0.0, A = 0.0, T = 0.0;
#pragma unroll
                for (int q = 0; q < 8; q++) { I += fin[0][q]; A += fin[1][q]; T += fin[2][q]; }
                loss += (T == 0.0) ? 0.0 : (1.0 - 2.0 * I / (A + T + 2.0e-6));
            }
            __syncthreads();
        }
        if (tid == 0) {
            out[0] = (float)(loss * 0.5);    // mean over BATCH=2
            g_ticket = 0;                    // reset for next graph replay
        }
    }
}

extern "C" void kernel_launch(void* const* d_in, const int* in_sizes, int n_in,
                              void* d_out, int out_size) {
    const float* outputs = (const float*)d_in[0];  // float32 [2,1,64,256,256]
    const int*   masks   = (const int*)d_in[1];    // int32   [2,1,64,256,256]
    float* out = (float*)d_out;

    pack_kernel<<<NCTA3, 256>>>(masks);
    cascade_kernel<<<SLICES, 1024>>>();
    decode_kernel<<<NCTA3, 256>>>(outputs, out);
}

// round 8
// speedup vs baseline: 1.5104x; 1.5104x over previous
#include <cuda_runtime.h>
#include <stdint.h>

// Geometry fixed by the problem: outputs/masks are [2,1,64,256,256]
#define HH 256
#define WW 256
#define BATCH 2
#define SLICES 128                 // 2*64 independent 2D slices
#define WPR 8                      // 32-bit words per 256-px row
#define NWORDS (HH * WPR)          // 2048 words per slice bitmask
#define NPIX (HH * WW)             // 65536 px per slice
#define NTHREADS 1024
#define NCHUNK 16                  // 16 chunks x 4096 px per slice

// Per-slice partial sums + rare slow-path plane spill
__device__ double   g_part[SLICES][3];
__device__ uint32_t g_pl[5][SLICES][NWORDS];   // written only for rare words
__device__ unsigned g_ticket = 0;

__device__ __forceinline__ void cp16(uint32_t saddr, const void* gptr) {
    asm volatile("cp.async.cg.shared.global [%0], [%1], 16;" :: "r"(saddr), "l"(gptr));
}
__device__ __forceinline__ void cp_commit() {
    asm volatile("cp.async.commit_group;");
}
template <int N>
__device__ __forceinline__ void cp_wait() {
    asm volatile("cp.async.wait_group %0;" :: "n"(N));
}

// dynamic smem layout (u32 words):
//  [0, 8192)      stream buffer: 2 slots x 1024 threads x 4 words (32 KB)
//                 (cascade double-buffer [0,2048)/[2048,4096) aliases slot 0)
//  [8192, 10240)  mb  - mask bits
//  [10240,12288)  eb  - edge bits
//  [12288,14336)  base_s - per-word LUT base (int), -100 = slow path
//  [14336,16384)  hm_s - per-word K==ktop bitmask
#define SM_STREAM 0
#define SM_MB     8192
#define SM_EB     10240
#define SM_BASE   12288
#define SM_HM     14336

__global__ __launch_bounds__(NTHREADS, 1)
void bbsd_fused_kernel(const float* __restrict__ outp, const int* __restrict__ mskp,
                       float* __restrict__ out) {
    extern __shared__ uint32_t dyn[];
    __shared__ float lut[64];
    __shared__ double red0[32], red1[32], red2[32];
    __shared__ int s_last;

    uint32_t* mb = dyn + SM_MB;
    uint32_t* eb = dyn + SM_EB;
    int*      base_s = reinterpret_cast<int*>(dyn + SM_BASE);
    uint32_t* hm_s = dyn + SM_HM;

    const int slice = blockIdx.x;
    const size_t base = (size_t)slice * NPIX;
    const int tid = threadIdx.x;
    const int lane = tid & 31;
    const int wid = tid >> 5;

    const uint32_t sm_base_u32 =
        (uint32_t)__cvta_generic_to_shared(dyn + SM_STREAM);
    const uint32_t slot_addr0 = sm_base_u32 + tid * 16u;          // slot 0
    const uint32_t slot_addr1 = sm_base_u32 + (4096u + tid * 4u) * 4u; // slot 1
    uint32_t* slot_p0 = dyn + SM_STREAM + tid * 4;
    uint32_t* slot_p1 = dyn + SM_STREAM + 4096 + tid * 4;

    // weight LUT: acc 0..21; dist=(22-acc)/22; w=2/(1+exp(10*dist)); padded
    if (tid < 64) {
        int a = tid < 22 ? tid : 21;
        float dist = (22.0f - (float)a) / 22.0f;
        lut[tid] = 2.0f / (1.0f + expf(10.0f * dist));
    }

    // ================= Phase 1: pack masks (cp.async pipeline) =================
    const int* mp = mskp + base;
    cp16(slot_addr0, mp + 0 * 4096 + tid * 4); cp_commit();
    cp16(slot_addr1, mp + 1 * 4096 + tid * 4); cp_commit();
#pragma unroll
    for (int k = 0; k < NCHUNK; k++) {
        if (k < NCHUNK - 1) cp_wait<1>(); else cp_wait<0>();
        uint32_t* sp = (k & 1) ? slot_p1 : slot_p0;
        uint32_t x0 = sp[0], x1 = sp[1], x2 = sp[2], x3 = sp[3];
        if (k + 2 < NCHUNK) {
            cp16((k & 1) ? slot_addr1 : slot_addr0, mp + (k + 2) * 4096 + tid * 4);
            cp_commit();
        }
        unsigned nib = (x0 ? 1u : 0u) | (x1 ? 2u : 0u) | (x2 ? 4u : 0u) | (x3 ? 8u : 0u);
        unsigned w = nib << ((lane & 7) * 4);
        w |= __shfl_xor_sync(0xffffffffu, w, 1);
        w |= __shfl_xor_sync(0xffffffffu, w, 2);
        w |= __shfl_xor_sync(0xffffffffu, w, 4);
        int g = k * NTHREADS + tid;
        if ((lane & 7) == 0) mb[g >> 3] = w;
    }
    __syncthreads();

    // ================= Phase 2: edge + cascade (smem bitmask) =================
    const int row = tid >> 2;
    const int cw0 = (tid & 3) * 2;
    const int wb = row * WPR + cw0;

    uint32_t P0[2], P1[2], P2[2], P3[2], P4[2];  // coverage K, bit-sliced

#pragma unroll
    for (int j = 0; j < 2; j++) {
        int cw = cw0 + j, gw = wb + j;
        uint32_t m  = mb[gw];
        uint32_t up = row            ? mb[gw - WPR] : 0u;
        uint32_t dn = (row < HH - 1) ? mb[gw + WPR] : 0u;
        uint32_t pv = cw             ? mb[gw - 1]   : 0u;
        uint32_t nx = (cw < WPR - 1) ? mb[gw + 1]   : 0u;
        uint32_t lf = (m << 1) | (pv >> 31);
        uint32_t rt = (m >> 1) | (nx << 31);
        uint32_t e = m & ~(up & dn & lf & rt);
        dyn[gw] = e;                         // cascade buffer 0 (aliases stream)
        eb[gw] = e;
        P0[j] = 0u; P1[j] = 0u; P2[j] = 0u; P3[j] = 0u; P4[j] = 0u;
    }
    __syncthreads();

    int extra = 0;
    int sb = 0;
    for (int r = 1; r <= 20; r++) {
        const uint32_t* src = dyn + sb * 2048;
        uint32_t* dst = dyn + (sb ^ 1) * 2048;
        uint32_t va[4];
#pragma unroll
        for (int k = 0; k < 4; k++) {
            int cw = cw0 + k - 1;
            uint32_t v = 0u;
            if (cw >= 0 && cw < WPR) {
                int gw = row * WPR + cw;
                v = src[gw];
                if (row)          v |= src[gw - WPR];
                if (row < HH - 1) v |= src[gw + WPR];
            }
            va[k] = v;
        }
        uint32_t allw = 0xffffffffu;
#pragma unroll
        for (int j = 0; j < 2; j++) {
            uint32_t c = va[j + 1];
            uint32_t nw = c | (c << 1) | (va[j] >> 31) | (c >> 1) | (va[j + 2] << 31);
            dst[wb + j] = nw;
            allw &= nw;
            uint32_t cy = nw, t;             // ripple-carry +1 where covered
            t = P0[j] & cy; P0[j] ^= cy; cy = t;
            t = P1[j] & cy; P1[j] ^= cy; cy = t;
            t = P2[j] & cy; P2[j] ^= cy; cy = t;
            t = P3[j] & cy; P3[j] ^= cy; cy = t;
            P4[j] ^= cy;
        }
        sb ^= 1;
        if (__syncthreads_and(allw == 0xffffffffu)) { extra = 20 - r; break; }
    }

    // per-word decode metadata: acc = K + edge with K in {kt-1, kt} (typical)
#pragma unroll
    for (int j = 0; j < 2; j++) {
        int gw = wb + j;
        uint32_t p0 = P0[j], p1 = P1[j], p2 = P2[j], p3 = P3[j], p4 = P4[j];
        unsigned kt = ((p0 >> 31) & 1u) | (((p1 >> 31) & 1u) << 1)
                    | (((p2 >> 31) & 1u) << 2) | (((p3 >> 31) & 1u) << 3)
                    | (((p4 >> 31) & 1u) << 4);
        uint32_t mhi = ((kt & 1u)  ? p0 : ~p0) & ((kt & 2u)  ? p1 : ~p1)
                     & ((kt & 4u)  ? p2 : ~p2) & ((kt & 8u)  ? p3 : ~p3)
                     & ((kt & 16u) ? p4 : ~p4);
        uint32_t mlo = 0u;
        if (kt) {
            unsigned kl = kt - 1u;
            mlo = ((kl & 1u)  ? p0 : ~p0) & ((kl & 2u)  ? p1 : ~p1)
                & ((kl & 4u)  ? p2 : ~p2) & ((kl & 8u)  ? p3 : ~p3)
                & ((kl & 16u) ? p4 : ~p4);
        }
        bool valid = (mhi | mlo) == 0xffffffffu;
        base_s[gw] = valid ? ((int)kt - 1 + extra) : -100;
        hm_s[gw] = mhi;
        if (!valid) {                        // rare: spill planes to gmem
            g_pl[0][slice][gw] = p0;
            g_pl[1][slice][gw] = p1;
            g_pl[2][slice][gw] = p2;
            g_pl[3][slice][gw] = p3;
            g_pl[4][slice][gw] = p4;
        }
    }
    __syncthreads();   // meta visible; cascade buffers dead -> stream reuse OK

    // ============ Phase 3: decode outputs (cp.async pipeline, no barriers) =====
    const float* op = outp + base;
    float s_ia = 0.f, s_in = 0.f, s_ta = 0.f;

    cp16(slot_addr0, op + 0 * 4096 + tid * 4); cp_commit();
    cp16(slot_addr1, op + 1 * 4096 + tid * 4); cp_commit();
#pragma unroll
    for (int k = 0; k < NCHUNK; k++) {
        if (k < NCHUNK - 1) cp_wait<1>(); else cp_wait<0>();
        uint32_t* sp = (k & 1) ? slot_p1 : slot_p0;
        float vv[4];
        vv[0] = __uint_as_float(sp[0]);
        vv[1] = __uint_as_float(sp[1]);
        vv[2] = __uint_as_float(sp[2]);
        vv[3] = __uint_as_float(sp[3]);
        if (k + 2 < NCHUNK) {
            cp16((k & 1) ? slot_addr1 : slot_addr0, op + (k + 2) * 4096 + tid * 4);
            cp_commit();
        }
        int g = k * NTHREADS + tid;          // float4 group; 8 lanes share a word
        int lw = g >> 3;
        int i0 = (g & 7) * 4;
        int wbase = base_s[lw];
        uint32_t qm = mb[lw] >> i0;
        uint32_t qe = eb[lw] >> i0;
        if (wbase != -100) {
            uint32_t qh = hm_s[lw] >> i0;
#pragma unroll
            for (int e = 0; e < 4; e++) {
                int idx = wbase + (int)((qh >> e) & 1u) + (int)((qe >> e) & 1u);
                float w = lut[idx];
                float f = vv[e] * w;
                s_ia += f;
                if ((qm >> e) & 1u) { s_in += f; s_ta += w; }
            }
        } else {
            uint32_t q0 = g_pl[0][slice][lw] >> i0;
            uint32_t q1 = g_pl[1][slice][lw] >> i0;
            uint32_t q2 = g_pl[2][slice][lw] >> i0;
            uint32_t q3 = g_pl[3][slice][lw] >> i0;
            uint32_t q4 = g_pl[4][slice][lw] >> i0;
#pragma unroll
            for (int e = 0; e < 4; e++) {
                unsigned a = ((q0 >> e) & 1u)
                           | (((q1 >> e) & 1u) << 1)
                           | (((q2 >> e) & 1u) << 2)
                           | (((q3 >> e) & 1u) << 3)
                           | (((q4 >> e) & 1u) << 4);
                a += ((qe >> e) & 1u) + extra;
                float w = lut[a];
                float f = vv[e] * w;
                s_ia += f;
                if ((qm >> e) & 1u) { s_in += f; s_ta += w; }
            }
        }
    }

    // ================= reduce to per-slice partials =================
    double d0 = (double)s_in, d1 = (double)s_ia, d2 = (double)s_ta;
#pragma unroll
    for (int o = 16; o > 0; o >>= 1) {
        d0 += __shfl_down_sync(0xffffffffu, d0, o);
        d1 += __shfl_down_sync(0xffffffffu, d1, o);
        d2 += __shfl_down_sync(0xffffffffu, d2, o);
    }
    if (lane == 0) { red0[wid] = d0; red1[wid] = d1; red2[wid] = d2; }
    __syncthreads();
    if (wid == 0) {
        double a0 = red0[lane];
        double a1 = red1[lane];
        double a2 = red2[lane];
#pragma unroll
        for (int o = 16; o > 0; o >>= 1) {
            a0 += __shfl_down_sync(0xffffffffu, a0, o);
            a1 += __shfl_down_sync(0xffffffffu, a1, o);
            a2 += __shfl_down_sync(0xffffffffu, a2, o);
        }
        if (lane == 0) {
            g_part[slice][0] = a0;
            g_part[slice][1] = a1;
            g_part[slice][2] = a2;
        }
    }

    // ================= fused finalize (last-arriving CTA) =================
    if (tid == 0) {
        __threadfence();
        unsigned t = atomicAdd(&g_ticket, 1u);
        s_last = (t == SLICES - 1);
    }
    __syncthreads();
    if (s_last && wid == 0) {
        __threadfence();
        double loss = 0.0;
#pragma unroll
        for (int b = 0; b < BATCH; b++) {
            double i0 = g_part[b * 64 + lane][0] + g_part[b * 64 + 32 + lane][0];
            double a0 = g_part[b * 64 + lane][1] + g_part[b * 64 + 32 + lane][1];
            double t0 = g_part[b * 64 + lane][2] + g_part[b * 64 + 32 + lane][2];
#pragma unroll
            for (int o = 16; o > 0; o >>= 1) {
                i0 += __shfl_down_sync(0xffffffffu, i0, o);
                a0 += __shfl_down_sync(0xffffffffu, a0, o);
                t0 += __shfl_down_sync(0xffffffffu, t0, o);
            }
            if (lane == 0)
                loss += (t0 == 0.0) ? 0.0 : (1.0 - 2.0 * i0 / (a0 + t0 + 2.0e-6));
        }
        if (lane == 0) {
            out[0] = (float)(loss * 0.5);    // mean over BATCH=2
            g_ticket = 0;                    // reset for next graph replay
        }
    }
}

extern "C" void kernel_launch(void* const* d_in, const int* in_sizes, int n_in,
                              void* d_out, int out_size) {
    const float* outputs = (const float*)d_in[0];  // float32 [2,1,64,256,256]
    const int*   masks   = (const int*)d_in[1];    // int32   [2,1,64,256,256]
    float* out = (float*)d_out;

    cudaFuncSetAttribute(bbsd_fused_kernel,
                         cudaFuncAttributeMaxDynamicSharedMemorySize, 65536);
    bbsd_fused_kernel<<<SLICES, NTHREADS, 65536>>>(outputs, masks, out);
}